// round 5
// baseline (speedup 1.0000x reference)
#include <cuda_runtime.h>
#include <cstdint>

#define NN 20000
#define MM 64
#define WL 8
#define NPAIRS (MM*NN*WL)      /* 10,240,000 pairs per X tensor */
#define NPB 32                 /* n's per chunk */
#define NCHUNK (NN/NPB)        /* 625 */
#define GX 74                  /* 74 x 2 batch-pairs = 148 blocks = 1/SM */
#define NT 1024                /* 32 warps */

// ---- shared memory layout (bytes) ----
#define SZ_TAB   (NN*8)          /* 160000: a-table, float2 per n            */
#define SZ_F1    (MM*33*8)       /* 16896 : F1[j][n], pad 33                 */
#define SZ_F2T   (NPB*66*8)      /* 16896 : F2T[n][k], pad 66 (even -> 16B)  */
#define SZ_PIP   (2048*8)        /* 16384 : piP[k/2][j] = {pi[j][k],pi[j][k+1]} */
#define SZ_P12   (2*MM*4)        /* 512   */
#define SZ_RED   (NPB*2*8)       /* 512   */
#define OFF_F1   SZ_TAB
#define OFF_F2T  (OFF_F1+SZ_F1)
#define OFF_PIP  (OFF_F2T+SZ_F2T)
#define OFF_P12  (OFF_PIP+SZ_PIP)
#define OFF_RED  (OFF_P12+SZ_P12)
#define SMEM_TOTAL (OFF_RED+SZ_RED)   /* 211200 */

// ---------------- device scratch (static) ------------------------------------
__device__ unsigned g_cx1[NPAIRS];   // packed (i0 | i1<<16)
__device__ unsigned g_cx2[NPAIRS];
__device__ float2   g_tabA[2*NN];    // [bp][n] = {a[2bp][n], a[2bp+1][n]}
__device__ float2   g_tabB[2*NN];
__device__ float2   g_piP[2048];     // [kp*64+j] = {pi[j][2kp], pi[j][2kp+1]}
__device__ float    g_pi1[MM];
__device__ float    g_pi2[MM];
__device__ int      g_is64;
__device__ int      g_tick[4];       // [iter*2+bp] chunk tickets

// ---------------- f32x2 helpers ----------------------------------------------
__device__ __forceinline__ unsigned long long pack2(float lo, float hi) {
    unsigned long long r;
    asm("mov.b64 %0, {%1, %2};" : "=l"(r) : "f"(lo), "f"(hi));
    return r;
}
__device__ __forceinline__ float2 unpack2(unsigned long long v) {
    float2 f;
    asm("mov.b64 {%0, %1}, %2;" : "=f"(f.x), "=f"(f.y) : "l"(v));
    return f;
}
__device__ __forceinline__ void fma2(unsigned long long& d, unsigned long long a, unsigned long long b) {
    asm("fma.rn.f32x2 %0, %1, %2, %0;" : "+l"(d) : "l"(a), "l"(b));
}
__device__ __forceinline__ unsigned long long mul2(unsigned long long a, unsigned long long b) {
    unsigned long long r;
    asm("mul.rn.f32x2 %0, %1, %2;" : "=l"(r) : "l"(a), "l"(b));
    return r;
}

// ---------------- setup: softmax | dtype detect | a-table | tickets ----------
__global__ void k_setup(const float* __restrict__ a0,
                        const float* __restrict__ Wm,
                        const unsigned* __restrict__ x1u) {
    int tid = threadIdx.x;
    if (blockIdx.x == 0) {
        __shared__ float sp[MM*MM];
        __shared__ float rbuf[256];
        float lm = -1e30f;
        for (int i = tid; i < MM*MM; i += 256) { float v = Wm[i]; sp[i] = v; lm = fmaxf(lm, v); }
        rbuf[tid] = lm; __syncthreads();
        for (int s = 128; s > 0; s >>= 1) { if (tid < s) rbuf[tid] = fmaxf(rbuf[tid], rbuf[tid+s]); __syncthreads(); }
        float m = rbuf[0]; __syncthreads();
        float ls = 0.f;
        for (int i = tid; i < MM*MM; i += 256) { float e = expf(sp[i] - m); sp[i] = e; ls += e; }
        rbuf[tid] = ls; __syncthreads();
        for (int s = 128; s > 0; s >>= 1) { if (tid < s) rbuf[tid] += rbuf[tid+s]; __syncthreads(); }
        float inv = 1.f / rbuf[0]; __syncthreads();
        for (int i = tid; i < MM*MM; i += 256) sp[i] *= inv;
        __syncthreads();
        // paired-k layout for phase 2
        for (int i = tid; i < 2048; i += 256) {
            int kp = i >> 6, j = i & 63;
            g_piP[i] = make_float2(sp[j*MM + 2*kp], sp[j*MM + 2*kp + 1]);
        }
        if (tid < MM) {
            float s = 0.f;
            for (int k = 0; k < MM; k++) s += sp[tid*MM + k];
            g_pi1[tid] = s;
        } else if (tid < 2*MM) {
            int k = tid - MM;
            float s = 0.f;
            for (int j = 0; j < MM; j++) s += sp[j*MM + k];
            g_pi2[k] = s;
        }
    } else if (blockIdx.x == 1) {
        __shared__ int s_nz;
        if (tid == 0) s_nz = 0;
        __syncthreads();
        int nz = 0;
        for (int t = tid; t < 2048; t += 256)
            nz |= (x1u[2*t + 1] != 0u);
        if (nz) atomicOr(&s_nz, 1);
        __syncthreads();
        if (tid == 0) g_is64 = s_nz ? 0 : 1;
        if (tid < 4) g_tick[tid] = 0;      // reset chunk tickets every launch
    } else {
        int i = (blockIdx.x - 2) * 256 + tid;
        if (i < NN) {
            g_tabA[i]      = make_float2(a0[i],        a0[NN + i]);
            g_tabA[NN + i] = make_float2(a0[2*NN + i], a0[3*NN + i]);
        }
    }
}

// ---------------- gather-max helper ------------------------------------------
__device__ __forceinline__ void gath_acc(unsigned v, const unsigned long long* __restrict__ tab,
                                         float2& f) {
    unsigned long long p = mul2(tab[v & 0xFFFFu], tab[v >> 16]);
    float2 q = unpack2(p);
    f.x = fmaxf(f.x, q.x);
    f.y = fmaxf(f.y, q.y);
}

// ---------------- main iteration kernel --------------------------------------
__global__ void __launch_bounds__(NT, 1) k_main(int iter,
                                                const void* __restrict__ x1,
                                                const void* __restrict__ x2,
                                                float* __restrict__ out) {
    extern __shared__ char smem[];
    float2* tab  = (float2*)smem;                    // [NN]
    float2* F1s  = (float2*)(smem + OFF_F1);         // [64][33]
    float2* F2T  = (float2*)(smem + OFF_F2T);        // [32][66]  (n-major, k inner)
    float2* piP  = (float2*)(smem + OFF_PIP);        // [32][64]
    float*  pi1s = (float*)(smem + OFF_P12);
    float*  pi2s = pi1s + MM;
    float2* red  = (float2*)(smem + OFF_RED);        // [32][2]
    __shared__ int s_chunk;

    const int bp  = blockIdx.y;
    const float2* __restrict__ src = iter ? g_tabB : g_tabA;
    float2*       __restrict__ dst = iter ? g_tabA : g_tabB;
    const int tid = threadIdx.x;
    const int is64 = g_is64;

    for (int i = tid; i < NN; i += NT) tab[i] = src[bp*NN + i];
    for (int i = tid; i < 2048; i += NT) piP[i] = g_piP[i];
    if (tid < MM) { pi1s[tid] = g_pi1[tid]; pi2s[tid] = g_pi2[tid]; }

    const unsigned long long* tabq = (const unsigned long long*)tab;
    const int warp = tid >> 5, lane = tid & 31;
    const int jj = tid & 63, grp = tid >> 6;         // grp 0..15
    const int half = warp & 1;
    int* tick = &g_tick[iter*2 + bp];

    for (;;) {
        if (tid == 0) s_chunk = atomicAdd(tick, 1);
        __syncthreads();                             // ticket + F/red reuse barrier
        const int chunk = s_chunk;
        if (chunk >= NCHUNK) break;
        const int n0 = chunk * NPB;

        // ======== phase 1: gather-max -> F1[j][n], F2T[n][k] ========
        #pragma unroll
        for (int p = 0; p < 2; p++) {
            const int j = p*32 + warp;
            const int n = n0 + lane;
            const size_t pb = ((size_t)j * NN + n) * WL;
            unsigned pk1[8], pk2[8];
            if (iter == 0) {
                if (is64) {
                    const uint4* c1 = (const uint4*)x1 + pb;
                    const uint4* c2 = (const uint4*)x2 + pb;
                    #pragma unroll
                    for (int w = 0; w < 8; w++) { uint4 v = __ldg(c1 + w); pk1[w] = v.x | (v.z << 16); }
                    #pragma unroll
                    for (int w = 0; w < 8; w++) { uint4 v = __ldg(c2 + w); pk2[w] = v.x | (v.z << 16); }
                } else {
                    const uint4* c1 = (const uint4*)x1 + (pb >> 1);
                    const uint4* c2 = (const uint4*)x2 + (pb >> 1);
                    #pragma unroll
                    for (int w = 0; w < 4; w++) {
                        uint4 v = __ldg(c1 + w);
                        pk1[2*w] = v.x | (v.y << 16); pk1[2*w+1] = v.z | (v.w << 16);
                    }
                    #pragma unroll
                    for (int w = 0; w < 4; w++) {
                        uint4 v = __ldg(c2 + w);
                        pk2[2*w] = v.x | (v.y << 16); pk2[2*w+1] = v.z | (v.w << 16);
                    }
                }
                if (bp == 0) {   // stash packed indices for iter 2
                    uint4* s1 = (uint4*)(g_cx1 + pb);
                    uint4* s2 = (uint4*)(g_cx2 + pb);
                    s1[0] = make_uint4(pk1[0], pk1[1], pk1[2], pk1[3]);
                    s1[1] = make_uint4(pk1[4], pk1[5], pk1[6], pk1[7]);
                    s2[0] = make_uint4(pk2[0], pk2[1], pk2[2], pk2[3]);
                    s2[1] = make_uint4(pk2[4], pk2[5], pk2[6], pk2[7]);
                }
            } else {
                const uint4* c1 = (const uint4*)(g_cx1 + pb);
                const uint4* c2 = (const uint4*)(g_cx2 + pb);
                uint4 q0 = __ldg(c1), q1 = __ldg(c1 + 1);
                uint4 r0 = __ldg(c2), r1 = __ldg(c2 + 1);
                pk1[0]=q0.x; pk1[1]=q0.y; pk1[2]=q0.z; pk1[3]=q0.w;
                pk1[4]=q1.x; pk1[5]=q1.y; pk1[6]=q1.z; pk1[7]=q1.w;
                pk2[0]=r0.x; pk2[1]=r0.y; pk2[2]=r0.z; pk2[3]=r0.w;
                pk2[4]=r1.x; pk2[5]=r1.y; pk2[6]=r1.z; pk2[7]=r1.w;
            }
            float2 f1 = make_float2(0.f, 0.f);   // products >= 0
            float2 f2 = make_float2(0.f, 0.f);
            #pragma unroll
            for (int w = 0; w < 8; w++) gath_acc(pk1[w], tabq, f1);
            #pragma unroll
            for (int w = 0; w < 8; w++) gath_acc(pk2[w], tabq, f2);
            F1s[j*33 + lane] = f1;
            F2T[lane*66 + j] = f2;
        }
        __syncthreads();

        // ======== phase 2: derived = pi1.F1 + pi2.F2 - F1.(pi@F2) ========
        {
            unsigned long long mv0 = 0ull, mv1 = 0ull;   // {0.f,0.f} bitwise
            const unsigned long long* f2a = (const unsigned long long*)&F2T[grp*66];
            const unsigned long long* f2b = (const unsigned long long*)&F2T[(grp+16)*66];
            #pragma unroll 8
            for (int kp = 0; kp < 32; kp++) {
                float2 pw = piP[kp*64 + jj];
                unsigned long long pw0 = pack2(pw.x, pw.x);
                unsigned long long pw1 = pack2(pw.y, pw.y);
                ulonglong2 A = *(const ulonglong2*)(f2a + 2*kp);   // k=2kp, 2kp+1 (16B aligned)
                ulonglong2 Bv = *(const ulonglong2*)(f2b + 2*kp);
                fma2(mv0, pw0, A.x);  fma2(mv0, pw1, A.y);
                fma2(mv1, pw0, Bv.x); fma2(mv1, pw1, Bv.y);
            }
            const float p1 = pi1s[jj], p2 = pi2s[jj];
            float2 mva = unpack2(mv0), mvb = unpack2(mv1);
            float2 f1a = F1s[jj*33 + grp],       f2ae = F2T[grp*66 + jj];
            float2 f1b = F1s[jj*33 + grp + 16],  f2be = F2T[(grp+16)*66 + jj];
            float2 c0, c1;
            c0.x = p1*f1a.x + p2*f2ae.x - f1a.x*mva.x;
            c0.y = p1*f1a.y + p2*f2ae.y - f1a.y*mva.y;
            c1.x = p1*f1b.x + p2*f2be.x - f1b.x*mvb.x;
            c1.y = p1*f1b.y + p2*f2be.y - f1b.y*mvb.y;
            #pragma unroll
            for (int off = 16; off > 0; off >>= 1) {
                c0.x += __shfl_xor_sync(0xFFFFFFFFu, c0.x, off);
                c0.y += __shfl_xor_sync(0xFFFFFFFFu, c0.y, off);
                c1.x += __shfl_xor_sync(0xFFFFFFFFu, c1.x, off);
                c1.y += __shfl_xor_sync(0xFFFFFFFFu, c1.y, off);
            }
            if (lane == 0) {
                red[grp*2 + half]        = c0;
                red[(grp+16)*2 + half]   = c1;
            }
        }
        __syncthreads();

        // ======== finalize: a' = 1 - (1-a)(1-derived) ========
        if (tid < NPB) {
            const int nl = tid;
            const int n  = n0 + nl;
            float2 d0 = red[nl*2], d1 = red[nl*2 + 1];
            float dx = d0.x + d1.x, dy = d0.y + d1.y;
            float2 ao = tab[n];
            float2 an;
            an.x = 1.f - (1.f - ao.x) * (1.f - dx);
            an.y = 1.f - (1.f - ao.y) * (1.f - dy);
            dst[bp*NN + n] = an;
            if (iter) {
                out[(2*bp)*NN + n]     = an.x;
                out[(2*bp + 1)*NN + n] = an.y;
            }
        }
        // no trailing sync: next ticket barrier covers F/red reuse
    }
}

// ---------------- launcher ----------------------------------------------------
extern "C" void kernel_launch(void* const* d_in, const int* in_sizes, int n_in,
                              void* d_out, int out_size) {
    const float* a0 = (const float*)d_in[0];
    const float* Wm = (const float*)d_in[1];
    const void*  x1 = d_in[2];
    const void*  x2 = d_in[3];
    float* out = (float*)d_out;

    cudaFuncSetAttribute(k_main, cudaFuncAttributeMaxDynamicSharedMemorySize, SMEM_TOTAL);

    k_setup<<<2 + (NN + 255)/256, 256>>>(a0, Wm, (const unsigned*)x1);

    dim3 g(GX, 2);
    k_main<<<g, NT, SMEM_TOTAL>>>(0, x1, x2, out);   // iter 1: raw X -> packed + tabB
    k_main<<<g, NT, SMEM_TOTAL>>>(1, x1, x2, out);   // iter 2: packed -> tabA + d_out
}

// round 6
// speedup vs baseline: 1.0138x; 1.0138x over previous
#include <cuda_runtime.h>
#include <cstdint>

#define NN 20000
#define MM 64
#define WL 8
#define NPAIRS (MM*NN*WL)      /* 10,240,000 pairs per X tensor */
#define NPB 32                 /* n's per chunk */
#define NCHUNK (NN/NPB)        /* 625 */
#define GX 74                  /* 74 x 2 batch-pairs = 148 blocks = 1/SM */
#define NT 1024                /* 32 warps */

// ---- shared memory layout (bytes) ----
#define SZ_TAB   (NN*8)          /* 160000: a-table, float2 per n            */
#define SZ_F1    (MM*33*8)       /* 16896 : F1[j][n], pad 33 (doubles as softmax scratch) */
#define SZ_F2T   (NPB*66*8)      /* 16896 : F2T[n][k], pad 66 (even -> 16B)  */
#define SZ_PIP   (2048*8)        /* 16384 : piP[kp][j] = {pi[j][2kp],pi[j][2kp+1]} */
#define SZ_P12   (2*MM*4)        /* 512   */
#define SZ_RED   (NPB*2*8)       /* 512   */
#define OFF_F1   SZ_TAB
#define OFF_F2T  (OFF_F1+SZ_F1)
#define OFF_PIP  (OFF_F2T+SZ_F2T)
#define OFF_P12  (OFF_PIP+SZ_PIP)
#define OFF_RED  (OFF_P12+SZ_P12)
#define SMEM_TOTAL (OFF_RED+SZ_RED)   /* 211200 */

// ---------------- device scratch (static) ------------------------------------
__device__ unsigned g_cx1[NPAIRS];   // packed (i0 | i1<<16)
__device__ unsigned g_cx2[NPAIRS];
__device__ float2   g_tabB[2*NN];    // intermediate a after iter 0

// ---------------- gather-max helper ------------------------------------------
__device__ __forceinline__ void gath_acc(unsigned v, const float2* __restrict__ tab, float2& f) {
    float2 A  = tab[v & 0xFFFFu];
    float2 Bv = tab[v >> 16];
    f.x = fmaxf(f.x, A.x * Bv.x);
    f.y = fmaxf(f.y, A.y * Bv.y);
}

// ---------------- main iteration kernel --------------------------------------
__global__ void __launch_bounds__(NT, 1) k_main(int iter,
                                                const float* __restrict__ a0,
                                                const float* __restrict__ Wm,
                                                const void* __restrict__ x1,
                                                const void* __restrict__ x2,
                                                float* __restrict__ out) {
    extern __shared__ char smem[];
    float2* tab  = (float2*)smem;                    // [NN]
    float2* F1s  = (float2*)(smem + OFF_F1);         // [64][33]
    float*  sp   = (float*)(smem + OFF_F1);          // [4096] softmax scratch (preamble only)
    float2* F2T  = (float2*)(smem + OFF_F2T);        // [32][66]  (n-major, k inner)
    float2* piP  = (float2*)(smem + OFF_PIP);        // [32][64]
    float*  pi1s = (float*)(smem + OFF_P12);
    float*  pi2s = pi1s + MM;
    float2* red  = (float2*)(smem + OFF_RED);        // [32][2]
    float*  redf = (float*)(smem + OFF_RED);         // aliased for preamble reductions

    const int bp  = blockIdx.y;
    const int tid = threadIdx.x;
    const int warp = tid >> 5, lane = tid & 31;

    // ===== preamble: a-table =====
    if (iter == 0) {
        const float* r0 = a0 + (size_t)(2*bp) * NN;
        const float* r1 = a0 + (size_t)(2*bp + 1) * NN;
        for (int i = tid; i < NN; i += NT)
            tab[i] = make_float2(__ldg(r0 + i), __ldg(r1 + i));
    } else {
        for (int i = tid; i < NN; i += NT) tab[i] = g_tabB[bp*NN + i];
    }

    // ===== preamble: softmax over 64x64 W (per-block, redundant, parallel) =====
    float v4[4];
    float lm = -1e30f;
    #pragma unroll
    for (int t = 0; t < 4; t++) {
        float v = __ldg(Wm + tid + t*NT);
        v4[t] = v; sp[tid + t*NT] = v;
        lm = fmaxf(lm, v);
    }
    #pragma unroll
    for (int off = 16; off > 0; off >>= 1)
        lm = fmaxf(lm, __shfl_xor_sync(0xFFFFFFFFu, lm, off));
    if (lane == 0) redf[warp] = lm;
    __syncthreads();
    float m = -1e30f;
    #pragma unroll
    for (int w = 0; w < 32; w++) m = fmaxf(m, redf[w]);
    float ls = 0.f;
    #pragma unroll
    for (int t = 0; t < 4; t++) {
        float e = expf(v4[t] - m);
        sp[tid + t*NT] = e;
        ls += e;
    }
    #pragma unroll
    for (int off = 16; off > 0; off >>= 1)
        ls += __shfl_xor_sync(0xFFFFFFFFu, ls, off);
    __syncthreads();                 // redf max values consumed
    if (lane == 0) redf[32 + warp] = ls;
    __syncthreads();
    float tot = 0.f;
    #pragma unroll
    for (int w = 0; w < 32; w++) tot += redf[32 + w];
    const float inv = 1.f / tot;

    // paired-k layout + row/col sums (scaled by inv on the fly)
    for (int i = tid; i < 2048; i += NT) {
        int kp = i >> 6, j = i & 63;
        piP[i] = make_float2(sp[j*MM + 2*kp] * inv, sp[j*MM + 2*kp + 1] * inv);
    }
    if (tid < MM) {
        float s = 0.f;
        #pragma unroll 16
        for (int k = 0; k < MM; k++) s += sp[tid*MM + k];
        pi1s[tid] = s * inv;
    } else if (tid < 2*MM) {
        int k = tid - MM;
        float s = 0.f;
        #pragma unroll 16
        for (int j = 0; j < MM; j++) s += sp[j*MM + k];
        pi2s[k] = s * inv;
    }

    // ===== preamble: dtype probe (iter 0 only) =====
    int is64 = 0;
    if (iter == 0) {
        const unsigned* x1u = (const unsigned*)x1;
        int nz = (x1u[2*tid + 1] != 0u) | (x1u[2*(tid + NT) + 1] != 0u);
        is64 = !__syncthreads_or(nz);
    }
    __syncthreads();   // sp scratch (aliases F1s) free; piP/pi1s/pi2s visible

    const int jj = tid & 63, grp = tid >> 6;         // grp 0..15
    const int half = warp & 1;
    float2* __restrict__ dst = g_tabB + bp*NN;

    for (int chunk = blockIdx.x; chunk < NCHUNK; chunk += GX) {
        const int n0 = chunk * NPB;

        // ======== phase 1: gather-max -> F1[j][n], F2T[n][k] ========
        #pragma unroll
        for (int p = 0; p < 2; p++) {
            const int j = p*32 + warp;
            const int n = n0 + lane;
            const size_t pb = ((size_t)j * NN + n) * WL;
            unsigned pk1[8], pk2[8];
            if (iter == 0) {
                if (is64) {
                    const uint4* c1 = (const uint4*)x1 + pb;
                    const uint4* c2 = (const uint4*)x2 + pb;
                    #pragma unroll
                    for (int w = 0; w < 8; w++) { uint4 v = __ldg(c1 + w); pk1[w] = v.x | (v.z << 16); }
                    #pragma unroll
                    for (int w = 0; w < 8; w++) { uint4 v = __ldg(c2 + w); pk2[w] = v.x | (v.z << 16); }
                } else {
                    const uint4* c1 = (const uint4*)x1 + (pb >> 1);
                    const uint4* c2 = (const uint4*)x2 + (pb >> 1);
                    #pragma unroll
                    for (int w = 0; w < 4; w++) {
                        uint4 v = __ldg(c1 + w);
                        pk1[2*w] = v.x | (v.y << 16); pk1[2*w+1] = v.z | (v.w << 16);
                    }
                    #pragma unroll
                    for (int w = 0; w < 4; w++) {
                        uint4 v = __ldg(c2 + w);
                        pk2[2*w] = v.x | (v.y << 16); pk2[2*w+1] = v.z | (v.w << 16);
                    }
                }
                if (bp == 0) {   // stash packed indices for iter 2
                    uint4* s1 = (uint4*)(g_cx1 + pb);
                    uint4* s2 = (uint4*)(g_cx2 + pb);
                    s1[0] = make_uint4(pk1[0], pk1[1], pk1[2], pk1[3]);
                    s1[1] = make_uint4(pk1[4], pk1[5], pk1[6], pk1[7]);
                    s2[0] = make_uint4(pk2[0], pk2[1], pk2[2], pk2[3]);
                    s2[1] = make_uint4(pk2[4], pk2[5], pk2[6], pk2[7]);
                }
            } else {
                const uint4* c1 = (const uint4*)(g_cx1 + pb);
                const uint4* c2 = (const uint4*)(g_cx2 + pb);
                uint4 q0 = __ldg(c1), q1 = __ldg(c1 + 1);
                uint4 r0 = __ldg(c2), r1 = __ldg(c2 + 1);
                pk1[0]=q0.x; pk1[1]=q0.y; pk1[2]=q0.z; pk1[3]=q0.w;
                pk1[4]=q1.x; pk1[5]=q1.y; pk1[6]=q1.z; pk1[7]=q1.w;
                pk2[0]=r0.x; pk2[1]=r0.y; pk2[2]=r0.z; pk2[3]=r0.w;
                pk2[4]=r1.x; pk2[5]=r1.y; pk2[6]=r1.z; pk2[7]=r1.w;
            }
            float2 f1 = make_float2(0.f, 0.f);   // products >= 0
            float2 f2 = make_float2(0.f, 0.f);
            #pragma unroll
            for (int w = 0; w < 8; w++) gath_acc(pk1[w], tab, f1);
            #pragma unroll
            for (int w = 0; w < 8; w++) gath_acc(pk2[w], tab, f2);
            F1s[j*33 + lane] = f1;
            F2T[lane*66 + j] = f2;
        }
        __syncthreads();

        // ======== phase 2: derived = pi1.F1 + pi2.F2 - F1.(pi@F2) ========
        {
            float2 mv0 = make_float2(0.f, 0.f), mv1 = make_float2(0.f, 0.f);
            const float4* f2a = (const float4*)&F2T[grp*66];        // [kp] -> k=2kp,2kp+1
            const float4* f2b = (const float4*)&F2T[(grp+16)*66];
            #pragma unroll 8
            for (int kp = 0; kp < 32; kp++) {
                float2 pw = piP[kp*64 + jj];
                float4 A  = f2a[kp];
                float4 Bv = f2b[kp];
                mv0.x = fmaf(pw.x, A.x,  mv0.x); mv0.y = fmaf(pw.x, A.y,  mv0.y);
                mv0.x = fmaf(pw.y, A.z,  mv0.x); mv0.y = fmaf(pw.y, A.w,  mv0.y);
                mv1.x = fmaf(pw.x, Bv.x, mv1.x); mv1.y = fmaf(pw.x, Bv.y, mv1.y);
                mv1.x = fmaf(pw.y, Bv.z, mv1.x); mv1.y = fmaf(pw.y, Bv.w, mv1.y);
            }
            const float p1 = pi1s[jj], p2 = pi2s[jj];
            float2 f1a = F1s[jj*33 + grp],       f2ae = F2T[grp*66 + jj];
            float2 f1b = F1s[jj*33 + grp + 16],  f2be = F2T[(grp+16)*66 + jj];
            float2 c0, c1;
            c0.x = p1*f1a.x + p2*f2ae.x - f1a.x*mv0.x;
            c0.y = p1*f1a.y + p2*f2ae.y - f1a.y*mv0.y;
            c1.x = p1*f1b.x + p2*f2be.x - f1b.x*mv1.x;
            c1.y = p1*f1b.y + p2*f2be.y - f1b.y*mv1.y;
            #pragma unroll
            for (int off = 16; off > 0; off >>= 1) {
                c0.x += __shfl_xor_sync(0xFFFFFFFFu, c0.x, off);
                c0.y += __shfl_xor_sync(0xFFFFFFFFu, c0.y, off);
                c1.x += __shfl_xor_sync(0xFFFFFFFFu, c1.x, off);
                c1.y += __shfl_xor_sync(0xFFFFFFFFu, c1.y, off);
            }
            if (lane == 0) {
                red[grp*2 + half]      = c0;
                red[(grp+16)*2 + half] = c1;
            }
        }
        __syncthreads();

        // ======== finalize: a' = 1 - (1-a)(1-derived) ========
        if (tid < NPB) {
            const int nl = tid;
            const int n  = n0 + nl;
            float2 d0 = red[nl*2], d1 = red[nl*2 + 1];
            float dx = d0.x + d1.x, dy = d0.y + d1.y;
            float2 ao = tab[n];
            float2 an;
            an.x = 1.f - (1.f - ao.x) * (1.f - dx);
            an.y = 1.f - (1.f - ao.y) * (1.f - dy);
            if (iter == 0) {
                dst[n] = an;
            } else {
                out[(2*bp)*NN + n]     = an.x;
                out[(2*bp + 1)*NN + n] = an.y;
            }
        }
        __syncthreads();
    }
}

// ---------------- launcher ----------------------------------------------------
extern "C" void kernel_launch(void* const* d_in, const int* in_sizes, int n_in,
                              void* d_out, int out_size) {
    const float* a0 = (const float*)d_in[0];
    const float* Wm = (const float*)d_in[1];
    const void*  x1 = d_in[2];
    const void*  x2 = d_in[3];
    float* out = (float*)d_out;

    cudaFuncSetAttribute(k_main, cudaFuncAttributeMaxDynamicSharedMemorySize, SMEM_TOTAL);

    dim3 g(GX, 2);
    k_main<<<g, NT, SMEM_TOTAL>>>(0, a0, Wm, x1, x2, out);  // iter 1: raw X -> packed + tabB
    k_main<<<g, NT, SMEM_TOTAL>>>(1, a0, Wm, x1, x2, out);  // iter 2: packed -> out
}

// round 7
// speedup vs baseline: 1.3910x; 1.3720x over previous
#include <cuda_runtime.h>
#include <cuda_fp16.h>
#include <cstdint>

#define NN 20000
#define MM 64
#define WL 8
#define NPAIRS (MM*NN*WL)      /* 10,240,000 pairs per X tensor */
#define NPB 32                 /* n's per chunk */
#define NCHUNK (NN/NPB)        /* 625 */
#define NBLK 148               /* one block per SM */
#define NT 512                 /* 16 warps */

// ---- shared memory layout (bytes) ----
#define SZ_TAB   (NN*8)          /* 160000: ushort4 a-table, 4 batches/entry */
#define OFF_F1   SZ_TAB          /* 160000 */
#define SZ_F1    (MM*33*8)       /* 16896 : F1[j][n] as half4 (uint2), pad 33 */
#define OFF_F2   (OFF_F1+SZ_F1)  /* 176896 (16B aligned) */
#define SZ_F2    (NPB*67*16)     /* 34304 : F2[n][k] float4, pad 67 (conflict-free) */
#define OFF_PIP  (OFF_F2+SZ_F2)  /* 211200 */
#define SZ_PIP   (2048*4)        /* 8192  : piP[kp*64+j] half2 = (pi[j][2kp],pi[j][2kp+1]) */
#define OFF_P12  (OFF_PIP+SZ_PIP)/* 219392 */
#define SZ_P12   (2*MM*4)        /* 512   */
#define OFF_RED  (OFF_P12+SZ_P12)/* 219904 */
#define SZ_RED   (NPB*2*16)      /* 1024  : float4[32][2] */
#define SMEM_TOTAL (OFF_RED+SZ_RED)  /* 220928 */

#define INV16   (1.0f/65535.0f)
#define FSCALE  (INV16*INV16)

// ---------------- device scratch (static) ------------------------------------
__device__ unsigned g_cx1[NPAIRS];   // packed (i0 | i1<<16)
__device__ unsigned g_cx2[NPAIRS];
__device__ ushort4  g_tabB[NN];      // intermediate a after iter 0 (u16 x 4 batches)
__device__ int      g_tick[2] = {0, 0};

// ---------------- helpers ------------------------------------------------------
__device__ __forceinline__ unsigned short q16(float a) {
    return (unsigned short)__float2uint_rn(__saturatef(a) * 65535.0f);
}
__device__ __forceinline__ void gath4(unsigned v, const ushort4* __restrict__ tab, float4& f) {
    ushort4 A = tab[v & 0xFFFFu];
    ushort4 B = tab[v >> 16];
    f.x = fmaxf(f.x, (float)A.x * (float)B.x);
    f.y = fmaxf(f.y, (float)A.y * (float)B.y);
    f.z = fmaxf(f.z, (float)A.z * (float)B.z);
    f.w = fmaxf(f.w, (float)A.w * (float)B.w);
}

// ---------------- main iteration kernel --------------------------------------
__global__ void __launch_bounds__(NT, 1) k_main(int iter,
                                                const float* __restrict__ a0,
                                                const float* __restrict__ Wm,
                                                const void* __restrict__ x1,
                                                const void* __restrict__ x2,
                                                float* __restrict__ out) {
    extern __shared__ char smem[];
    ushort4*  tabu = (ushort4*)smem;                  // [NN]
    uint2*    F1h  = (uint2*) (smem + OFF_F1);        // [64][33] half4
    float*    sp   = (float*) (smem + OFF_F1);        // [4096] softmax scratch (preamble)
    float4*   F2f  = (float4*)(smem + OFF_F2);        // [32][67]
    __half2*  piPh = (__half2*)(smem + OFF_PIP);      // [32*64]
    float*    pi1s = (float*) (smem + OFF_P12);
    float*    pi2s = pi1s + MM;
    float4*   red4 = (float4*)(smem + OFF_RED);       // [32][2]
    float*    redf = (float*) (smem + OFF_RED);       // preamble reductions / finalize
    __shared__ int s_chunk;

    const int tid  = threadIdx.x;
    const int warp = tid >> 5, lane = tid & 31;

    // reset the OTHER iter's ticket for the next launch/replay (safe: unused here)
    if (blockIdx.x == 0 && tid == 0) g_tick[iter ^ 1] = 0;

    // ===== preamble: quantized 4-batch a-table =====
    if (iter == 0) {
        for (int i = tid; i < NN; i += NT) {
            float v0 = __ldg(a0 + i);
            float v1 = __ldg(a0 + NN + i);
            float v2 = __ldg(a0 + 2*NN + i);
            float v3 = __ldg(a0 + 3*NN + i);
            tabu[i] = make_ushort4(q16(v0), q16(v1), q16(v2), q16(v3));
        }
    } else {
        for (int i = tid; i < NN; i += NT) tabu[i] = g_tabB[i];
    }

    // ===== preamble: softmax over 64x64 W (per-block, parallel) =====
    float v8[8];
    float lm = -1e30f;
    #pragma unroll
    for (int t = 0; t < 8; t++) {
        float v = __ldg(Wm + tid + t*NT);
        v8[t] = v;
        lm = fmaxf(lm, v);
    }
    #pragma unroll
    for (int off = 16; off > 0; off >>= 1)
        lm = fmaxf(lm, __shfl_xor_sync(0xFFFFFFFFu, lm, off));
    if (lane == 0) redf[warp] = lm;
    __syncthreads();
    float m = -1e30f;
    #pragma unroll
    for (int w = 0; w < 16; w++) m = fmaxf(m, redf[w]);
    __syncthreads();
    float ls = 0.f;
    #pragma unroll
    for (int t = 0; t < 8; t++) {
        float e = expf(v8[t] - m);
        sp[tid + t*NT] = e;
        ls += e;
    }
    #pragma unroll
    for (int off = 16; off > 0; off >>= 1)
        ls += __shfl_xor_sync(0xFFFFFFFFu, ls, off);
    if (lane == 0) redf[16 + warp] = ls;
    __syncthreads();
    float tot = 0.f;
    #pragma unroll
    for (int w = 0; w < 16; w++) tot += redf[16 + w];
    const float inv = 1.f / tot;

    // piP (half2 paired-k), pi1, pi2
    for (int i = tid; i < 2048; i += NT) {
        int kp = i >> 6, j = i & 63;
        piPh[i] = __floats2half2_rn(sp[j*MM + 2*kp] * inv, sp[j*MM + 2*kp + 1] * inv);
    }
    if (tid < MM) {
        float s = 0.f;
        #pragma unroll 16
        for (int k = 0; k < MM; k++) s += sp[tid*MM + k];
        pi1s[tid] = s * inv;
    } else if (tid < 2*MM) {
        int k = tid - MM;
        float s = 0.f;
        #pragma unroll 16
        for (int j = 0; j < MM; j++) s += sp[j*MM + k];
        pi2s[k] = s * inv;
    }

    // ===== preamble: dtype probe (iter 0 only) =====
    int is64 = 0;
    if (iter == 0) {
        const unsigned* x1u = (const unsigned*)x1;
        int nz = (x1u[2*tid + 1] != 0u) | (x1u[2*(tid + NT) + 1] != 0u);
        is64 = !__syncthreads_or(nz);
    }
    __syncthreads();   // sp scratch dead; tab/piP/pi1/pi2 visible

    const int jj = tid & 63, g8 = tid >> 6;   // phase-2 mapping
    const int half = warp & 1;
    int* tick = &g_tick[iter];

    for (;;) {
        if (tid == 0) s_chunk = atomicAdd(tick, 1);
        __syncthreads();
        const int chunk = s_chunk;
        if (chunk >= NCHUNK) break;
        const int n0 = chunk * NPB;

        // ======== phase 1: 4-batch gather-max -> F1[j][n] (half4), F2[n][k] (float4) ========
        #pragma unroll
        for (int p = 0; p < 4; p++) {
            const int j = p*16 + warp;
            const size_t pb = ((size_t)j * NN + n0 + lane) * WL;
            unsigned pk1[8], pk2[8];
            if (iter == 0) {
                if (is64) {
                    const uint4* c1 = (const uint4*)x1 + pb;
                    const uint4* c2 = (const uint4*)x2 + pb;
                    #pragma unroll
                    for (int w = 0; w < 8; w++) { uint4 v = __ldcs(c1 + w); pk1[w] = v.x | (v.z << 16); }
                    #pragma unroll
                    for (int w = 0; w < 8; w++) { uint4 v = __ldcs(c2 + w); pk2[w] = v.x | (v.z << 16); }
                } else {
                    const uint4* c1 = (const uint4*)x1 + (pb >> 1);
                    const uint4* c2 = (const uint4*)x2 + (pb >> 1);
                    #pragma unroll
                    for (int w = 0; w < 4; w++) {
                        uint4 v = __ldcs(c1 + w);
                        pk1[2*w] = v.x | (v.y << 16); pk1[2*w+1] = v.z | (v.w << 16);
                    }
                    #pragma unroll
                    for (int w = 0; w < 4; w++) {
                        uint4 v = __ldcs(c2 + w);
                        pk2[2*w] = v.x | (v.y << 16); pk2[2*w+1] = v.z | (v.w << 16);
                    }
                }
                // stash packed indices for iter 2 (each chunk owned by exactly one block)
                uint4* s1 = (uint4*)(g_cx1 + pb);
                uint4* s2 = (uint4*)(g_cx2 + pb);
                s1[0] = make_uint4(pk1[0], pk1[1], pk1[2], pk1[3]);
                s1[1] = make_uint4(pk1[4], pk1[5], pk1[6], pk1[7]);
                s2[0] = make_uint4(pk2[0], pk2[1], pk2[2], pk2[3]);
                s2[1] = make_uint4(pk2[4], pk2[5], pk2[6], pk2[7]);
            } else {
                const uint4* c1 = (const uint4*)(g_cx1 + pb);
                const uint4* c2 = (const uint4*)(g_cx2 + pb);
                uint4 q0 = __ldg(c1), q1 = __ldg(c1 + 1);
                uint4 r0 = __ldg(c2), r1 = __ldg(c2 + 1);
                pk1[0]=q0.x; pk1[1]=q0.y; pk1[2]=q0.z; pk1[3]=q0.w;
                pk1[4]=q1.x; pk1[5]=q1.y; pk1[6]=q1.z; pk1[7]=q1.w;
                pk2[0]=r0.x; pk2[1]=r0.y; pk2[2]=r0.z; pk2[3]=r0.w;
                pk2[4]=r1.x; pk2[5]=r1.y; pk2[6]=r1.z; pk2[7]=r1.w;
            }
            float4 f1 = make_float4(0.f, 0.f, 0.f, 0.f);   // products >= 0
            float4 f2 = make_float4(0.f, 0.f, 0.f, 0.f);
            #pragma unroll
            for (int w = 0; w < 8; w++) gath4(pk1[w], tabu, f1);
            #pragma unroll
            for (int w = 0; w < 8; w++) gath4(pk2[w], tabu, f2);
            // rescale to true units; F1 -> half4, F2 -> float4
            __half2 h01 = __floats2half2_rn(f1.x * FSCALE, f1.y * FSCALE);
            __half2 h23 = __floats2half2_rn(f1.z * FSCALE, f1.w * FSCALE);
            uint2 hp;
            hp.x = *(unsigned*)&h01;
            hp.y = *(unsigned*)&h23;
            F1h[j*33 + lane] = hp;
            F2f[lane*67 + j] = make_float4(f2.x*FSCALE, f2.y*FSCALE, f2.z*FSCALE, f2.w*FSCALE);
        }
        __syncthreads();

        // ======== phase 2: derived = pi1.F1 + pi2.F2 - F1.(pi@F2), 4 batches ========
        {
            float4 mv[4];
            #pragma unroll
            for (int r = 0; r < 4; r++) mv[r] = make_float4(0.f, 0.f, 0.f, 0.f);
            #pragma unroll 4
            for (int kp = 0; kp < 32; kp++) {
                float2 pw = __half22float2(piPh[kp*64 + jj]);
                #pragma unroll
                for (int r = 0; r < 4; r++) {
                    const int n = r*8 + g8;
                    float4 A  = F2f[n*67 + 2*kp];       // warp-broadcast
                    float4 B  = F2f[n*67 + 2*kp + 1];
                    mv[r].x = fmaf(pw.x, A.x, mv[r].x); mv[r].y = fmaf(pw.x, A.y, mv[r].y);
                    mv[r].z = fmaf(pw.x, A.z, mv[r].z); mv[r].w = fmaf(pw.x, A.w, mv[r].w);
                    mv[r].x = fmaf(pw.y, B.x, mv[r].x); mv[r].y = fmaf(pw.y, B.y, mv[r].y);
                    mv[r].z = fmaf(pw.y, B.z, mv[r].z); mv[r].w = fmaf(pw.y, B.w, mv[r].w);
                }
            }
            const float p1 = pi1s[jj], p2 = pi2s[jj];
            #pragma unroll
            for (int r = 0; r < 4; r++) {
                const int n = r*8 + g8;
                uint2 hp = F1h[jj*33 + n];
                float2 f01 = __half22float2(*(__half2*)&hp.x);
                float2 f23 = __half22float2(*(__half2*)&hp.y);
                float4 f2v = F2f[n*67 + jj];
                float4 c;
                c.x = p1*f01.x + p2*f2v.x - f01.x*mv[r].x;
                c.y = p1*f01.y + p2*f2v.y - f01.y*mv[r].y;
                c.z = p1*f23.x + p2*f2v.z - f23.x*mv[r].z;
                c.w = p1*f23.y + p2*f2v.w - f23.y*mv[r].w;
                #pragma unroll
                for (int off = 16; off > 0; off >>= 1) {
                    c.x += __shfl_xor_sync(0xFFFFFFFFu, c.x, off);
                    c.y += __shfl_xor_sync(0xFFFFFFFFu, c.y, off);
                    c.z += __shfl_xor_sync(0xFFFFFFFFu, c.z, off);
                    c.w += __shfl_xor_sync(0xFFFFFFFFu, c.w, off);
                }
                if (lane == 0) red4[n*2 + half] = c;
            }
        }
        __syncthreads();

        // ======== finalize: a' = 1 - (1-a)(1-derived) ========
        if (iter == 0) {
            if (tid < NPB) {
                const int n = n0 + tid;
                float4 d0 = red4[tid*2], d1 = red4[tid*2 + 1];
                ushort4 u = tabu[n];
                float4 an;
                an.x = 1.f - (1.f - (float)u.x*INV16) * (1.f - (d0.x + d1.x));
                an.y = 1.f - (1.f - (float)u.y*INV16) * (1.f - (d0.y + d1.y));
                an.z = 1.f - (1.f - (float)u.z*INV16) * (1.f - (d0.z + d1.z));
                an.w = 1.f - (1.f - (float)u.w*INV16) * (1.f - (d0.w + d1.w));
                g_tabB[n] = make_ushort4(q16(an.x), q16(an.y), q16(an.z), q16(an.w));
            }
        } else {
            if (tid < 4*NPB) {
                const int b = tid >> 5, nl = tid & 31;
                const int n = n0 + nl;
                float dv = redf[nl*8 + b] + redf[nl*8 + 4 + b];
                float av = (float)((const unsigned short*)smem)[n*4 + b] * INV16;
                out[b*NN + n] = 1.f - (1.f - av) * (1.f - dv);
            }
        }
        // next ticket barrier covers red/F reuse
    }
}

// ---------------- launcher ----------------------------------------------------
extern "C" void kernel_launch(void* const* d_in, const int* in_sizes, int n_in,
                              void* d_out, int out_size) {
    const float* a0 = (const float*)d_in[0];
    const float* Wm = (const float*)d_in[1];
    const void*  x1 = d_in[2];
    const void*  x2 = d_in[3];
    float* out = (float*)d_out;

    cudaFuncSetAttribute(k_main, cudaFuncAttributeMaxDynamicSharedMemorySize, SMEM_TOTAL);

    k_main<<<NBLK, NT, SMEM_TOTAL>>>(0, a0, Wm, x1, x2, out);  // iter 1: raw X -> packed + tabB
    k_main<<<NBLK, NT, SMEM_TOTAL>>>(1, a0, Wm, x1, x2, out);  // iter 2: packed -> out
}

// round 8
// speedup vs baseline: 1.5679x; 1.1272x over previous
#include <cuda_runtime.h>
#include <cuda_fp16.h>
#include <cstdint>

#define NN 20000
#define MM 64
#define WL 8
#define NPAIRS (MM*NN*WL)      /* 10,240,000 pairs per X tensor */
#define NPB 32                 /* n's per chunk */
#define NCHUNK (NN/NPB)        /* 625 */
#define NBLK 148               /* one block per SM */
#define NT 1024                /* 32 warps */

// ---- shared memory layout (bytes) ----
#define SZ_TAB   (NN*8)          /* 160000: uint2 = {half2(b0,b1), half2(b2,b3)} */
#define OFF_F1   SZ_TAB          /* 160000 */
#define SZ_F1    (MM*33*8)       /* 16896 : F1[j][n] half4 (uint2), pad 33 */
#define OFF_F2   (OFF_F1+SZ_F1)  /* 176896 */
#define SZ_F2    (NPB*67*16)     /* 34304 : F2[n][k] float4, pad 67 */
#define OFF_PIP  (OFF_F2+SZ_F2)  /* 211200 */
#define SZ_PIP   (2048*4)        /* 8192  : piP[kp*64+j] half2 */
#define OFF_P12  (OFF_PIP+SZ_PIP)/* 219392 */
#define SZ_P12   (2*MM*4)        /* 512   */
#define OFF_RED  (OFF_P12+SZ_P12)/* 219904 */
#define SZ_RED   (NPB*2*16)      /* 1024  : float4[32][2] */
#define SMEM_TOTAL (OFF_RED+SZ_RED)  /* 220928 */

typedef unsigned long long ull;

// ---------------- device scratch (static) ------------------------------------
__device__ unsigned g_cx1[NPAIRS];   // packed (i0 | i1<<16)
__device__ unsigned g_cx2[NPAIRS];
__device__ uint2    g_tabB[NN];      // intermediate a after iter 0 (half x 4 batches)
__device__ int      g_tick[2] = {0, 0};

// ---------------- f32x2 helpers ----------------------------------------------
__device__ __forceinline__ ull pack2(float lo, float hi) {
    ull r; asm("mov.b64 %0, {%1, %2};" : "=l"(r) : "f"(lo), "f"(hi)); return r;
}
__device__ __forceinline__ float2 unpack2(ull v) {
    float2 f; asm("mov.b64 {%0, %1}, %2;" : "=f"(f.x), "=f"(f.y) : "l"(v)); return f;
}
__device__ __forceinline__ void fma2(ull& d, ull a, ull b) {
    asm("fma.rn.f32x2 %0, %1, %2, %0;" : "+l"(d) : "l"(a), "l"(b));
}

// ---------------- half gather-max --------------------------------------------
__device__ __forceinline__ void gath_h(unsigned v, const uint2* __restrict__ tab,
                                       __half2& a01, __half2& a23) {
    uint2 A = tab[v & 0xFFFFu];
    uint2 B = tab[v >> 16];
    a01 = __hmax2(a01, __hmul2(*(__half2*)&A.x, *(__half2*)&B.x));
    a23 = __hmax2(a23, __hmul2(*(__half2*)&A.y, *(__half2*)&B.y));
}

// ---------------- main iteration kernel --------------------------------------
__global__ void __launch_bounds__(NT, 1) k_main(int iter,
                                                const float* __restrict__ a0,
                                                const float* __restrict__ Wm,
                                                const void* __restrict__ x1,
                                                const void* __restrict__ x2,
                                                float* __restrict__ out) {
    extern __shared__ char smem[];
    uint2*    tabh = (uint2*)smem;                    // [NN]
    uint2*    F1h  = (uint2*) (smem + OFF_F1);        // [64][33] half4
    float*    sp   = (float*) (smem + OFF_F1);        // [4096] softmax scratch (preamble)
    float4*   F2f  = (float4*)(smem + OFF_F2);        // [32][67]
    __half2*  piPh = (__half2*)(smem + OFF_PIP);      // [32*64]
    float*    pi1s = (float*) (smem + OFF_P12);
    float*    pi2s = pi1s + MM;
    float4*   red4 = (float4*)(smem + OFF_RED);       // [32][2]
    float*    redf = (float*) (smem + OFF_RED);
    __shared__ int s_chunk;

    const int tid  = threadIdx.x;
    const int warp = tid >> 5, lane = tid & 31;

    // reset the OTHER iter's ticket for the next launch/replay
    if (blockIdx.x == 0 && tid == 0) g_tick[iter ^ 1] = 0;

    // ===== preamble: half 4-batch a-table =====
    if (iter == 0) {
        for (int i = tid; i < NN; i += NT) {
            __half2 h01 = __floats2half2_rn(__ldg(a0 + i),      __ldg(a0 + NN + i));
            __half2 h23 = __floats2half2_rn(__ldg(a0 + 2*NN + i), __ldg(a0 + 3*NN + i));
            tabh[i] = make_uint2(*(unsigned*)&h01, *(unsigned*)&h23);
        }
    } else {
        for (int i = tid; i < NN; i += NT) tabh[i] = g_tabB[i];
    }

    // ===== preamble: softmax over 64x64 W (per-block, parallel) =====
    {
        float v4[4];
        float lm = -1e30f;
        #pragma unroll
        for (int t = 0; t < 4; t++) {
            float v = __ldg(Wm + tid + t*NT);
            v4[t] = v;
            lm = fmaxf(lm, v);
        }
        #pragma unroll
        for (int off = 16; off > 0; off >>= 1)
            lm = fmaxf(lm, __shfl_xor_sync(0xFFFFFFFFu, lm, off));
        if (lane == 0) redf[warp] = lm;
        __syncthreads();
        float m = -1e30f;
        #pragma unroll
        for (int w = 0; w < 32; w++) m = fmaxf(m, redf[w]);
        __syncthreads();
        float ls = 0.f;
        #pragma unroll
        for (int t = 0; t < 4; t++) {
            float e = expf(v4[t] - m);
            sp[tid + t*NT] = e;
            ls += e;
        }
        #pragma unroll
        for (int off = 16; off > 0; off >>= 1)
            ls += __shfl_xor_sync(0xFFFFFFFFu, ls, off);
        if (lane == 0) redf[32 + warp] = ls;
        __syncthreads();
        float tot = 0.f;
        #pragma unroll
        for (int w = 0; w < 32; w++) tot += redf[32 + w];
        const float inv = 1.f / tot;

        for (int i = tid; i < 2048; i += NT) {
            int kp = i >> 6, j = i & 63;
            piPh[i] = __floats2half2_rn(sp[j*MM + 2*kp] * inv, sp[j*MM + 2*kp + 1] * inv);
        }
        if (tid < MM) {
            float s = 0.f;
            #pragma unroll 16
            for (int k = 0; k < MM; k++) s += sp[tid*MM + k];
            pi1s[tid] = s * inv;
        } else if (tid < 2*MM) {
            int k = tid - MM;
            float s = 0.f;
            #pragma unroll 16
            for (int j = 0; j < MM; j++) s += sp[j*MM + k];
            pi2s[k] = s * inv;
        }
    }

    // ===== preamble: dtype probe (iter 0 only) =====
    int is64 = 0;
    if (iter == 0) {
        const unsigned* x1u = (const unsigned*)x1;
        int nz = (x1u[2*tid + 1] != 0u) | (x1u[2*(tid + NT) + 1] != 0u);
        is64 = !__syncthreads_or(nz);
    }
    __syncthreads();   // sp scratch dead; tab/piP/pi1/pi2 visible

    const int jj = tid & 63, g8 = tid >> 6;   // phase-2 mapping (g8: 0..15)
    const int half = warp & 1;
    int* tick = &g_tick[iter];

    for (;;) {
        if (tid == 0) s_chunk = atomicAdd(tick, 1);
        __syncthreads();
        const int chunk = s_chunk;
        if (chunk >= NCHUNK) break;
        const int n0 = chunk * NPB;

        // ======== phase 1: 4-batch half gather-max ========
        #pragma unroll
        for (int p = 0; p < 2; p++) {
            const int j = p*32 + warp;
            const size_t pb = ((size_t)j * NN + n0 + lane) * WL;
            __half2 f1a = __float2half2_rn(0.f), f1b = f1a;
            __half2 f2a = f1a, f2b = f1a;
            if (iter == 0) {
                unsigned pk[8];
                if (is64) {
                    const uint4* c1 = (const uint4*)x1 + pb;
                    #pragma unroll
                    for (int h = 0; h < 2; h++) {
                        uint4 v0 = __ldcs(c1+4*h), v1 = __ldcs(c1+4*h+1),
                              v2 = __ldcs(c1+4*h+2), v3 = __ldcs(c1+4*h+3);
                        pk[4*h]   = v0.x | (v0.z << 16);
                        pk[4*h+1] = v1.x | (v1.z << 16);
                        pk[4*h+2] = v2.x | (v2.z << 16);
                        pk[4*h+3] = v3.x | (v3.z << 16);
                    }
                } else {
                    const uint4* c1 = (const uint4*)x1 + (pb >> 1);
                    #pragma unroll
                    for (int w = 0; w < 4; w++) {
                        uint4 v = __ldcs(c1 + w);
                        pk[2*w] = v.x | (v.y << 16); pk[2*w+1] = v.z | (v.w << 16);
                    }
                }
                ((uint4*)(g_cx1 + pb))[0] = make_uint4(pk[0], pk[1], pk[2], pk[3]);
                ((uint4*)(g_cx1 + pb))[1] = make_uint4(pk[4], pk[5], pk[6], pk[7]);
                #pragma unroll
                for (int w = 0; w < 8; w++) gath_h(pk[w], tabh, f1a, f1b);

                if (is64) {
                    const uint4* c2 = (const uint4*)x2 + pb;
                    #pragma unroll
                    for (int h = 0; h < 2; h++) {
                        uint4 v0 = __ldcs(c2+4*h), v1 = __ldcs(c2+4*h+1),
                              v2 = __ldcs(c2+4*h+2), v3 = __ldcs(c2+4*h+3);
                        pk[4*h]   = v0.x | (v0.z << 16);
                        pk[4*h+1] = v1.x | (v1.z << 16);
                        pk[4*h+2] = v2.x | (v2.z << 16);
                        pk[4*h+3] = v3.x | (v3.z << 16);
                    }
                } else {
                    const uint4* c2 = (const uint4*)x2 + (pb >> 1);
                    #pragma unroll
                    for (int w = 0; w < 4; w++) {
                        uint4 v = __ldcs(c2 + w);
                        pk[2*w] = v.x | (v.y << 16); pk[2*w+1] = v.z | (v.w << 16);
                    }
                }
                ((uint4*)(g_cx2 + pb))[0] = make_uint4(pk[0], pk[1], pk[2], pk[3]);
                ((uint4*)(g_cx2 + pb))[1] = make_uint4(pk[4], pk[5], pk[6], pk[7]);
                #pragma unroll
                for (int w = 0; w < 8; w++) gath_h(pk[w], tabh, f2a, f2b);
            } else {
                const uint4* c1 = (const uint4*)(g_cx1 + pb);
                const uint4* c2 = (const uint4*)(g_cx2 + pb);
                uint4 q0 = __ldg(c1), q1 = __ldg(c1 + 1);
                uint4 r0 = __ldg(c2), r1 = __ldg(c2 + 1);
                gath_h(q0.x, tabh, f1a, f1b); gath_h(q0.y, tabh, f1a, f1b);
                gath_h(q0.z, tabh, f1a, f1b); gath_h(q0.w, tabh, f1a, f1b);
                gath_h(q1.x, tabh, f1a, f1b); gath_h(q1.y, tabh, f1a, f1b);
                gath_h(q1.z, tabh, f1a, f1b); gath_h(q1.w, tabh, f1a, f1b);
                gath_h(r0.x, tabh, f2a, f2b); gath_h(r0.y, tabh, f2a, f2b);
                gath_h(r0.z, tabh, f2a, f2b); gath_h(r0.w, tabh, f2a, f2b);
                gath_h(r1.x, tabh, f2a, f2b); gath_h(r1.y, tabh, f2a, f2b);
                gath_h(r1.z, tabh, f2a, f2b); gath_h(r1.w, tabh, f2a, f2b);
            }
            F1h[j*33 + lane] = make_uint2(*(unsigned*)&f1a, *(unsigned*)&f1b);
            float2 lo = __half22float2(f2a), hi = __half22float2(f2b);
            F2f[lane*67 + j] = make_float4(lo.x, lo.y, hi.x, hi.y);
        }
        __syncthreads();

        // ======== phase 2: derived = pi1.F1 + pi2.F2 - F1.(pi@F2), f32x2 ========
        {
            ull mv00 = 0ull, mv01 = 0ull, mv10 = 0ull, mv11 = 0ull;  // [n][b01/b23]
            const ulonglong2* fbA = (const ulonglong2*)(F2f + g8*67);
            const ulonglong2* fbB = (const ulonglong2*)(F2f + (g8+16)*67);
            #pragma unroll 4
            for (int kp = 0; kp < 32; kp++) {
                float2 pw = __half22float2(piPh[kp*64 + jj]);
                ull pwx = pack2(pw.x, pw.x);
                ull pwy = pack2(pw.y, pw.y);
                ulonglong2 A0 = fbA[2*kp], B0 = fbA[2*kp + 1];   // k=2kp, 2kp+1 (n=g8)
                ulonglong2 A1 = fbB[2*kp], B1 = fbB[2*kp + 1];   // (n=g8+16)
                fma2(mv00, pwx, A0.x); fma2(mv01, pwx, A0.y);
                fma2(mv00, pwy, B0.x); fma2(mv01, pwy, B0.y);
                fma2(mv10, pwx, A1.x); fma2(mv11, pwx, A1.y);
                fma2(mv10, pwy, B1.x); fma2(mv11, pwy, B1.y);
            }
            const float p1 = pi1s[jj], p2 = pi2s[jj];
            #pragma unroll
            for (int r = 0; r < 2; r++) {
                const int n = g8 + r*16;
                float2 ma = unpack2(r ? mv10 : mv00);
                float2 mb = unpack2(r ? mv11 : mv01);
                uint2 hp = F1h[jj*33 + n];
                float2 f01 = __half22float2(*(__half2*)&hp.x);
                float2 f23 = __half22float2(*(__half2*)&hp.y);
                float4 f2v = F2f[n*67 + jj];
                float4 c;
                c.x = p1*f01.x + p2*f2v.x - f01.x*ma.x;
                c.y = p1*f01.y + p2*f2v.y - f01.y*ma.y;
                c.z = p1*f23.x + p2*f2v.z - f23.x*mb.x;
                c.w = p1*f23.y + p2*f2v.w - f23.y*mb.y;
                #pragma unroll
                for (int off = 16; off > 0; off >>= 1) {
                    c.x += __shfl_xor_sync(0xFFFFFFFFu, c.x, off);
                    c.y += __shfl_xor_sync(0xFFFFFFFFu, c.y, off);
                    c.z += __shfl_xor_sync(0xFFFFFFFFu, c.z, off);
                    c.w += __shfl_xor_sync(0xFFFFFFFFu, c.w, off);
                }
                if (lane == 0) red4[n*2 + half] = c;
            }
        }
        __syncthreads();

        // ======== finalize: a' = 1 - (1-a)(1-derived) ========
        if (iter == 0) {
            if (tid < NPB) {
                const int n = n0 + tid;
                float4 d0 = red4[tid*2], d1 = red4[tid*2 + 1];
                uint2 u = tabh[n];
                float2 a01 = __half22float2(*(__half2*)&u.x);
                float2 a23 = __half22float2(*(__half2*)&u.y);
                __half2 h01 = __floats2half2_rn(
                    1.f - (1.f - a01.x) * (1.f - (d0.x + d1.x)),
                    1.f - (1.f - a01.y) * (1.f - (d0.y + d1.y)));
                __half2 h23 = __floats2half2_rn(
                    1.f - (1.f - a23.x) * (1.f - (d0.z + d1.z)),
                    1.f - (1.f - a23.y) * (1.f - (d0.w + d1.w)));
                g_tabB[n] = make_uint2(*(unsigned*)&h01, *(unsigned*)&h23);
            }
        } else {
            if (tid < 4*NPB) {
                const int b = tid >> 5, nl = tid & 31;
                const int n = n0 + nl;
                float dv = redf[nl*8 + b] + redf[nl*8 + 4 + b];
                float av = __half2float(((const __half*)smem)[n*4 + b]);
                out[b*NN + n] = 1.f - (1.f - av) * (1.f - dv);
            }
        }
        // next ticket barrier covers red/F reuse
    }
}

// ---------------- launcher ----------------------------------------------------
extern "C" void kernel_launch(void* const* d_in, const int* in_sizes, int n_in,
                              void* d_out, int out_size) {
    const float* a0 = (const float*)d_in[0];
    const float* Wm = (const float*)d_in[1];
    const void*  x1 = d_in[2];
    const void*  x2 = d_in[3];
    float* out = (float*)d_out;

    cudaFuncSetAttribute(k_main, cudaFuncAttributeMaxDynamicSharedMemorySize, SMEM_TOTAL);

    k_main<<<NBLK, NT, SMEM_TOTAL>>>(0, a0, Wm, x1, x2, out);  // iter 1: raw X -> packed + tabB
    k_main<<<NBLK, NT, SMEM_TOTAL>>>(1, a0, Wm, x1, x2, out);  // iter 2: packed -> out
}